// round 14
// baseline (speedup 1.0000x reference)
#include <cuda_runtime.h>
#include <stdint.h>
#include <math.h>

#define BATCH   8
#define NANCH   76725
#define NROWS   (BATCH*NANCH)
#define NC      80
#define NF      84
#define KMAX    100
#define CAP     512
#define NPAIR   (BATCH*NC)
#define FLOOR_LOGIT 2.8f
#define SCORE_TH 0.05f
#define IOU_THR 0.5f
#define CSH     5

typedef unsigned long long u64;
typedef unsigned int u32;

// scratch (BSS zero covers first call; classnms re-zeros g_cnt/g_img_arrive each launch)
__device__ int    g_cnt[NPAIR<<CSH];
__device__ u64    g_cand[NPAIR*CAP];        // (flip(logit)<<32) | (0x7FFFFFFF - n)
__device__ float  g_cls_scores[NPAIR*KMAX];
__device__ float  g_cls_boxes[NPAIR*KMAX*4];
__device__ float2 g_dims2[45];              // fp64-exact anchor dims (scan block 0 writes)
__device__ int    g_img_arrive[BATCH];

__device__ __forceinline__ float sigmoidf_(float x){ return 1.0f/(1.0f+expf(-x)); }
__device__ __forceinline__ u32 flip_f(u32 u){ return (u & 0x80000000u) ? ~u : (u | 0x80000000u); }
__device__ __forceinline__ float unflip_f(u32 u){
    return __uint_as_float((u & 0x80000000u) ? (u ^ 0x80000000u) : ~u);
}

// ================= sweep: warp-tiled ILP=4, streaming loads =================
__device__ __forceinline__ void scan_one(float4 v, int e){
    float m = fmaxf(fmaxf(v.x,v.y), fmaxf(v.z,v.w));
    if (m > FLOOR_LOGIT){
        int row = e/21, chunk = e - row*21;
        if (chunk){                                   // chunk 0 = box quad, skip
            int b = row/NANCH, n = row - b*NANCH;
            int pb = b*NC + (chunk-1)*4;
            float vv[4] = {v.x, v.y, v.z, v.w};
            #pragma unroll
            for (int q = 0; q < 4; q++){
                if (vv[q] > FLOOR_LOGIT){
                    int p = pb + q;
                    int slot = atomicAdd(&g_cnt[p<<CSH], 1);
                    if (slot < CAP)
                        g_cand[p*CAP + slot] =
                            ((u64)(__float_as_uint(vv[q]) | 0x80000000u) << 32) | (u32)(0x7FFFFFFF - n);
                }
            }
        }
    }
}

__global__ __launch_bounds__(256) void k_scan(const float4* __restrict__ pred4){
    if (blockIdx.x == 0 && threadIdx.x < 45){   // fp64-exact dims, once per launch
        int t = threadIdx.x;
        int lvl = t/9, k = t%9, ri = k/3, si = k%3;
        double side = 32.0 * (double)(1 << lvl);
        double area = side*side;
        double ratio = (ri==0) ? 0.5 : ((ri==1) ? 1.0 : 2.0);
        double scale = (si==0) ? 1.0 : ((si==1) ? 1.2599210498948732 : 1.5874010519681994);
        double ah = sqrt(area / ratio);
        double aw = area / ah;
        g_dims2[t] = make_float2((float)(scale*aw), (float)(scale*ah));
    }
    const int TOT = NROWS*21;                 // 12,889,800 float4s
    const int gtid = blockIdx.x*blockDim.x + threadIdx.x;
    const int lane = threadIdx.x & 31;
    const int warp_id = gtid >> 5;
    const int nwarps = (gridDim.x*blockDim.x) >> 5;
    const int n_tiles = TOT >> 7;             // 128-element warp tiles

    for (int tile = warp_id; tile < n_tiles; tile += nwarps){
        int e = (tile << 7) + lane;
        float4 v0 = __ldcs(pred4 + e);
        float4 v1 = __ldcs(pred4 + e + 32);
        float4 v2 = __ldcs(pred4 + e + 64);
        float4 v3 = __ldcs(pred4 + e + 96);
        scan_one(v0, e);
        scan_one(v1, e + 32);
        scan_one(v2, e + 64);
        scan_one(v3, e + 96);
    }
    int e = (n_tiles << 7) + gtid;
    if (e < TOT) scan_one(__ldcs(pred4 + e), e);
}

// descending bin scan shared by selects
__device__ __forceinline__ void radix_scan_bins(int* bins, u32 prefix, int need,
                                                u32* sh_pref, int* sh_need, int* sh_tc){
    int tid = threadIdx.x;
    if (tid < 32){
        int c[8]; int lsum = 0;
        #pragma unroll
        for (int j = 0; j < 8; j++){ c[j] = bins[(tid<<3)+j]; lsum += c[j]; }
        int acc = lsum;
        #pragma unroll
        for (int off = 1; off < 32; off <<= 1){
            int t2 = __shfl_down_sync(0xFFFFFFFFu, acc, off);
            if (tid + off < 32) acc += t2;
        }
        int cum = acc - lsum;
        #pragma unroll
        for (int j = 7; j >= 0; j--){
            int nx = cum + c[j];
            if (cum < need && need <= nx){
                *sh_pref = (prefix << 8) | (u32)((tid<<3) + j);
                *sh_need = need - cum;
                *sh_tc   = c[j];
            }
            cum = nx;
        }
    }
}

// ================= per (image,class): counting-sort rank + greedy NMS; last block merges =================
__global__ __launch_bounds__(256) void k_classnms(const float* __restrict__ pred,
                                                  float* __restrict__ out){
    const int p = blockIdx.x;
    const int tid = threadIdx.x;
    const int bimg = p / NC;

    __shared__ float2 s_dims[45];
    __shared__ int bins[256], base[256], cur[256];
    __shared__ int s_cnt, s_tbmin, s_tbmax;
    __shared__ u64 s_ord[CAP];
    __shared__ float4 sbox[KMAX];
    __shared__ float sarea[KMAX], ssc[KMAX];
    __shared__ u32 supw[KMAX*4];
    __shared__ u32 s_keep[4];
    __shared__ u32 sh_pref; __shared__ int sh_need, sh_tc, s_n;

    if (tid < 45) s_dims[tid] = g_dims2[tid];   // L2 hit, no FP64 here

    int cnt = g_cnt[p<<CSH];

    // exact fallback (block-uniform; never taken on this data, guards any data)
    if (cnt < KMAX || cnt > CAP){
        const int c = p % NC;
        const float* bptr = pred + (size_t)bimg*NANCH*NF + 4 + c;
        if (tid == 0) s_cnt = 0;
        __syncthreads();
        int loc = 0;
        for (int n = tid; n < NANCH; n += 256)
            if (sigmoidf_(bptr[(size_t)n*NF]) > SCORE_TH) loc++;
        atomicAdd(&s_cnt, loc);
        __syncthreads();
        int total = s_cnt;
        int T0 = min(total, KMAX);
        if (T0 == 0) cnt = 0;
        else {
            u64 lo = 0ull, hi = ~0ull;
            while (lo < hi){
                u64 mid = lo + ((hi - lo) >> 1) + 1ull;
                __syncthreads();
                if (tid == 0) s_cnt = 0;
                __syncthreads();
                int cc = 0;
                for (int n = tid; n < NANCH; n += 256){
                    float v = bptr[(size_t)n*NF];
                    if (sigmoidf_(v) > SCORE_TH){
                        u64 kk = ((u64)flip_f(__float_as_uint(v)) << 32) | (u32)(0x7FFFFFFF - n);
                        if (kk >= mid) cc++;
                    }
                }
                atomicAdd(&s_cnt, cc);
                __syncthreads();
                if (s_cnt >= T0) lo = mid; else hi = mid - 1;
            }
            __syncthreads();
            if (tid == 0) s_cnt = 0;
            __syncthreads();
            for (int n = tid; n < NANCH; n += 256){
                float v = bptr[(size_t)n*NF];
                if (sigmoidf_(v) > SCORE_TH){
                    u64 kk = ((u64)flip_f(__float_as_uint(v)) << 32) | (u32)(0x7FFFFFFF - n);
                    if (kk >= lo){
                        int sl = atomicAdd(&s_cnt, 1);
                        if (sl < CAP) g_cand[p*CAP + sl] = kk;
                    }
                }
            }
            cnt = T0;
        }
        __syncthreads();
    }

    const int T = min(cnt, KMAX);

    u64 key[2];
    #pragma unroll
    for (int q = 0; q < 2; q++){
        int s = tid + (q<<8);
        key[q] = (s < cnt) ? g_cand[p*CAP + s] : 0ull;
    }

    if (tid == 0){ s_tbmin = 256; s_tbmax = -1; }
    bins[tid] = 0;
    if (tid < KMAX){ ssc[tid] = -1.0f; sbox[tid] = make_float4(0,0,0,0); sarea[tid] = 0.0f; }
    if (tid < KMAX*4 - 256) supw[tid+256] = 0u;
    supw[tid] = 0u;
    __syncthreads();

    #pragma unroll
    for (int q = 0; q < 2; q++){
        if (key[q]){
            int tb = (int)((u32)(key[q] >> 56));
            atomicMin(&s_tbmin, tb);
            atomicMax(&s_tbmax, tb);
        }
    }
    __syncthreads();
    const bool by23 = (s_tbmin == s_tbmax);

    #pragma unroll
    for (int q = 0; q < 2; q++){
        if (key[q]){
            int b = by23 ? (int)((key[q] >> 48) & 255) : (int)((u32)(key[q] >> 56));
            atomicAdd(&bins[b], 1);
        }
    }
    __syncthreads();

    if (tid < 32){
        int c[8]; int lsum = 0;
        #pragma unroll
        for (int j = 0; j < 8; j++){ c[j] = bins[(tid<<3)+j]; lsum += c[j]; }
        int acc = lsum;
        #pragma unroll
        for (int off = 1; off < 32; off <<= 1){
            int t2 = __shfl_down_sync(0xFFFFFFFFu, acc, off);
            if (tid + off < 32) acc += t2;
        }
        int cum = acc - lsum;
        #pragma unroll
        for (int j = 7; j >= 0; j--){
            base[(tid<<3)+j] = cum;
            cur[(tid<<3)+j]  = cum;
            cum += c[j];
        }
    }
    __syncthreads();

    #pragma unroll
    for (int q = 0; q < 2; q++){
        if (key[q]){
            int b = by23 ? (int)((key[q] >> 48) & 255) : (int)((u32)(key[q] >> 56));
            int slot = atomicAdd(&cur[b], 1);
            s_ord[slot] = key[q];
        }
    }
    __syncthreads();

    #pragma unroll
    for (int q = 0; q < 2; q++){
        if (key[q]){
            u64 k = key[q];
            int b = by23 ? (int)((k >> 48) & 255) : (int)((u32)(k >> 56));
            int lo = base[b];
            if (lo < T){
                int hiB = lo + bins[b];
                int rank = lo;
                for (int t = lo; t < hiB; t++) rank += (s_ord[t] > k);
                if (rank < T){
                    float logit = unflip_f((u32)(k >> 32));
                    float sc = sigmoidf_(logit);
                    int n = 0x7FFFFFFF - (int)(u32)(k & 0xFFFFFFFFull);
                    int lvl = (n>=57600) + (n>=72000) + (n>=75600) + (n>=76500);
                    int off = (lvl==0)?0 : (lvl==1)?57600 : (lvl==2)?72000 : (lvl==3)?75600 : 76500;
                    int local = n - off;
                    int k9   = local % 9;
                    int cell = local / 9;
                    int sh = 4 - lvl;
                    int iy = (cell/5) >> sh;
                    int jx = cell - iy*(5<<sh);
                    float stridef = (float)(8<<lvl);
                    float2 d = s_dims[lvl*9 + k9];
                    float4 bp = __ldg((const float4*)pred + (size_t)(bimg*NANCH + n)*21);
                    float cx = ((float)jx + 0.5f)*stridef;
                    float cy = ((float)iy + 0.5f)*stridef;
                    float x  = (bp.x*0.1f)*d.x + cx;
                    float y  = (bp.y*0.1f)*d.y + cy;
                    float ww = expf(bp.z*0.2f)*d.x;
                    float hh = expf(bp.w*0.2f)*d.y;
                    float4 bx = make_float4(x - ww*0.5f, y - hh*0.5f, x + ww*0.5f, y + hh*0.5f);
                    ssc[rank] = sc;
                    sbox[rank] = bx;
                    sarea[rank] = (bx.z - bx.x)*(bx.w - bx.y);
                }
            }
        }
    }
    __syncthreads();

    for (int q = tid; q < (KMAX*(KMAX-1))/2; q += 256){
        int r = q / 50, m = q - r*50;
        int i, j;
        if (m == 0){ i = r; j = KMAX-1; }
        else {
            int a = r + m;            if (a >= KMAX-1) a -= (KMAX-1);
            int bb = r + (KMAX-1) - m; if (bb >= KMAX-1) bb -= (KMAX-1);
            i = min(a,bb); j = max(a,bb);
        }
        float4 A = sbox[i], B = sbox[j];
        float ltx = fmaxf(A.x,B.x), lty = fmaxf(A.y,B.y);
        float rbx = fminf(A.z,B.z), rby = fminf(A.w,B.w);
        float w = fmaxf(rbx-ltx, 0.0f), h = fmaxf(rby-lty, 0.0f);
        float inter = w*h;
        float iou = inter / (sarea[i] + sarea[j] - inter + 1e-8f);
        if (iou > IOU_THR)
            atomicOr(&supw[i*4 + (j>>5)], 1u << (j & 31));
    }
    __syncthreads();

    if (tid == 0){
        u32 keep[4];
        #pragma unroll
        for (int w = 0; w < 4; w++){
            int rem = T - w*32;
            keep[w] = (rem >= 32) ? 0xFFFFFFFFu : (rem <= 0 ? 0u : ((1u<<rem)-1u));
        }
        for (int i = 0; i < T; i++){
            if (keep[i>>5] & (1u << (i&31))){
                keep[0] &= ~supw[i*4+0]; keep[1] &= ~supw[i*4+1];
                keep[2] &= ~supw[i*4+2]; keep[3] &= ~supw[i*4+3];
            }
        }
        s_keep[0]=keep[0]; s_keep[1]=keep[1]; s_keep[2]=keep[2]; s_keep[3]=keep[3];
        g_cnt[p<<CSH] = 0;    // re-arm for next launch/replay
    }
    __syncthreads();
    if (tid < KMAX){
        bool kept = (tid < T) && (s_keep[tid>>5] & (1u << (tid&31)));
        g_cls_scores[p*KMAX + tid] = kept ? ssc[tid] : -1.0f;
        ((float4*)g_cls_boxes)[p*KMAX + tid] = sbox[tid];
    }

    // ---------- last block of each image performs the merge ----------
    __threadfence();
    if (tid == 0) s_cnt = atomicAdd(&g_img_arrive[bimg], 1);
    __syncthreads();
    if (s_cnt != NC-1) return;
    if (tid == 0) g_img_arrive[bimg] = 0;     // re-arm for replay

    const int M = NC*KMAX;                    // 8000
    const float* cs = g_cls_scores + bimg*M;

    // count positives (only positive keys can appear in output; npos<100 -> trailing zeros)
    if (tid == 0) s_n = 0;
    __syncthreads();
    int loc = 0;
    for (int it = 0; it < 32; it++){
        int s = tid + (it<<8);
        if (s < M && cs[s] > 0.0f) loc++;
    }
    for (int o = 16; o; o >>= 1) loc += __shfl_down_sync(0xFFFFFFFFu, loc, o);
    if ((tid & 31) == 0 && loc) atomicAdd(&s_n, loc);
    __syncthreads();
    const int npos = s_n;
    const int T2 = min(npos, KMAX);

    u64 mthr = ~0ull;
    if (T2 > 0){
        // 4-pass select on flipped score bits (positive keys only)
        u32 prefix = 0; int need = T2, tc = 0;
        for (int pass = 0; pass < 4; pass++){
            const int shift = 24 - (pass<<3);
            bins[tid] = 0;
            __syncthreads();
            for (int it = 0; it < 32; it++){
                int s = tid + (it<<8);
                if (s < M){
                    float sc = cs[s];
                    if (sc > 0.0f){
                        u32 f = __float_as_uint(sc) | 0x80000000u;
                        if (pass == 0 || (f >> (shift+8)) == prefix)
                            atomicAdd(&bins[(f >> shift) & 255], 1);
                    }
                }
            }
            __syncthreads();
            radix_scan_bins(bins, prefix, need, &sh_pref, &sh_need, &sh_tc);
            __syncthreads();
            prefix = sh_pref; need = sh_need; tc = sh_tc;
            __syncthreads();
        }
        u32 thr_lo = 0;
        if (tc != need){
            // tie on score bits: split by low word (0x7FFFFFFF - s), exact
            u32 prefix2 = 0; int need2 = need;
            for (int pass = 0; pass < 4; pass++){
                const int shift = 24 - (pass<<3);
                bins[tid] = 0;
                __syncthreads();
                for (int it = 0; it < 32; it++){
                    int s = tid + (it<<8);
                    if (s < M){
                        float sc = cs[s];
                        if (sc > 0.0f && (__float_as_uint(sc) | 0x80000000u) == prefix){
                            u32 f = (u32)(0x7FFFFFFF - s);
                            if (pass == 0 || (f >> (shift+8)) == prefix2)
                                atomicAdd(&bins[(f >> shift) & 255], 1);
                        }
                    }
                }
                __syncthreads();
                radix_scan_bins(bins, prefix2, need2, &sh_pref, &sh_need, &sh_tc);
                __syncthreads();
                prefix2 = sh_pref; need2 = sh_need;
                __syncthreads();
            }
            thr_lo = prefix2;
        }
        mthr = ((u64)prefix << 32) | thr_lo;
    }

    // compact winners, rank, output
    if (tid == 0) s_n = 0;
    if (tid < KMAX) s_ord[128 + tid] = 0ull;   // s_sorted region
    __syncthreads();
    if (T2 > 0){
        for (int it = 0; it < 32; it++){
            int s = tid + (it<<8);
            if (s < M){
                float sc = cs[s];
                if (sc > 0.0f){
                    u64 kk = ((u64)(__float_as_uint(sc) | 0x80000000u) << 32) | (u32)(0x7FFFFFFF - s);
                    if (kk >= mthr){
                        int pos = atomicAdd(&s_n, 1);
                        if (pos < 112) s_ord[pos] = kk;
                    }
                }
            }
        }
    }
    __syncthreads();
    const int mG = min(s_n, 112);
    if (tid < mG){
        u64 k = s_ord[tid];
        int rank = 0;
        for (int jj = 0; jj < mG; jj++) rank += (s_ord[jj] > k);
        if (rank < T2) s_ord[128 + rank] = k;
    }
    __syncthreads();

    if (tid < KMAX){
        u64 k = s_ord[128 + tid];
        bool good = (k != 0ull);
        float sc = 0.0f; float4 bx = make_float4(0,0,0,0); float clsf = 0.0f;
        if (good){
            sc = __uint_as_float((u32)(k >> 32) & 0x7FFFFFFFu);
            int s = 0x7FFFFFFF - (int)(u32)(k & 0xFFFFFFFFull);
            bx = ((const float4*)g_cls_boxes)[bimg*M + s];
            clsf = (float)(s / KMAX);
        }
        ((float4*)out)[bimg*KMAX + tid] = bx;                       // boxes  [0, 3200)
        out[BATCH*KMAX*4 + bimg*KMAX + tid] = sc;                   // scores [3200, 4000)
        out[BATCH*KMAX*5 + bimg*KMAX + tid] = clsf;                 // classes[4000, 4800)
    }
    if (tid == 0) out[BATCH*KMAX*6 + bimg] = (float)T2;             // valid  [4800, 4808)
}

extern "C" void kernel_launch(void* const* d_in, const int* in_sizes, int n_in,
                              void* d_out, int out_size){
    const float* pred = nullptr;
    const int PRED_SZ = BATCH*NANCH*NF;
    int best = -1;
    for (int i = 0; i < n_in; i++){
        if (in_sizes[i] == PRED_SZ){ pred = (const float*)d_in[i]; break; }
        if (best < 0 || in_sizes[i] > in_sizes[best]) best = i;
    }
    if (!pred) pred = (const float*)d_in[best < 0 ? 0 : best];

    float* out = (float*)d_out;
    (void)out_size;

    k_scan<<<2048, 256>>>((const float4*)pred);
    k_classnms<<<NPAIR, 256>>>(pred, out);
}

// round 15
// speedup vs baseline: 1.2356x; 1.2356x over previous
#include <cuda_runtime.h>
#include <stdint.h>
#include <math.h>

#define BATCH   8
#define NANCH   76725
#define NROWS   (BATCH*NANCH)
#define NC      80
#define NF      84
#define KMAX    100
#define CAP     512
#define NPAIR   (BATCH*NC)
#define FLOOR_LOGIT 2.8f
#define SCORE_TH 0.05f
#define IOU_THR 0.5f
#define CSH     5

typedef unsigned long long u64;
typedef unsigned int u32;

// scratch (BSS zero covers first call; classnms re-zeros g_cnt each launch)
__device__ int    g_cnt[NPAIR<<CSH];
__device__ u64    g_cand[NPAIR*CAP];        // (flip(logit)<<32) | (0x7FFFFFFF - n)
__device__ float  g_cls_scores[NPAIR*KMAX];
__device__ float  g_cls_boxes[NPAIR*KMAX*4];
__device__ float2 g_dims2[45];              // fp64-exact anchor dims (scan block 0 writes)

__device__ __forceinline__ float sigmoidf_(float x){ return 1.0f/(1.0f+expf(-x)); }
__device__ __forceinline__ u32 flip_f(u32 u){ return (u & 0x80000000u) ? ~u : (u | 0x80000000u); }
__device__ __forceinline__ float unflip_f(u32 u){
    return __uint_as_float((u & 0x80000000u) ? (u ^ 0x80000000u) : ~u);
}

// ================= sweep: warp-tiled ILP=4, streaming (evict-first) loads =================
__device__ __forceinline__ void scan_one(float4 v, int e){
    float m = fmaxf(fmaxf(v.x,v.y), fmaxf(v.z,v.w));
    if (m > FLOOR_LOGIT){
        int row = e/21, chunk = e - row*21;
        if (chunk){                                   // chunk 0 = box quad, skip
            int b = row/NANCH, n = row - b*NANCH;
            int pb = b*NC + (chunk-1)*4;
            float vv[4] = {v.x, v.y, v.z, v.w};
            #pragma unroll
            for (int q = 0; q < 4; q++){
                if (vv[q] > FLOOR_LOGIT){
                    int p = pb + q;
                    int slot = atomicAdd(&g_cnt[p<<CSH], 1);
                    if (slot < CAP)
                        g_cand[p*CAP + slot] =
                            ((u64)(__float_as_uint(vv[q]) | 0x80000000u) << 32) | (u32)(0x7FFFFFFF - n);
                }
            }
        }
    }
}

__global__ __launch_bounds__(256) void k_scan(const float4* __restrict__ pred4){
    if (blockIdx.x == 0 && threadIdx.x < 45){   // fp64-exact dims, once per launch (mem-bound kernel: free)
        int t = threadIdx.x;
        int lvl = t/9, k = t%9, ri = k/3, si = k%3;
        double side = 32.0 * (double)(1 << lvl);
        double area = side*side;
        double ratio = (ri==0) ? 0.5 : ((ri==1) ? 1.0 : 2.0);
        double scale = (si==0) ? 1.0 : ((si==1) ? 1.2599210498948732 : 1.5874010519681994);
        double ah = sqrt(area / ratio);
        double aw = area / ah;
        g_dims2[t] = make_float2((float)(scale*aw), (float)(scale*ah));
    }
    const int TOT = NROWS*21;                 // 12,889,800 float4s
    const int gtid = blockIdx.x*blockDim.x + threadIdx.x;
    const int lane = threadIdx.x & 31;
    const int warp_id = gtid >> 5;
    const int nwarps = (gridDim.x*blockDim.x) >> 5;
    const int n_tiles = TOT >> 7;             // 128-element warp tiles

    for (int tile = warp_id; tile < n_tiles; tile += nwarps){
        int e = (tile << 7) + lane;
        float4 v0 = __ldcs(pred4 + e);
        float4 v1 = __ldcs(pred4 + e + 32);
        float4 v2 = __ldcs(pred4 + e + 64);
        float4 v3 = __ldcs(pred4 + e + 96);
        scan_one(v0, e);
        scan_one(v1, e + 32);
        scan_one(v2, e + 64);
        scan_one(v3, e + 96);
    }
    // tail: TOT % 128 elements
    int e = (n_tiles << 7) + gtid;
    if (e < TOT) scan_one(__ldcs(pred4 + e), e);
}

// ================= radix machinery (used by merge only) =================
__device__ __forceinline__ void radix_scan_bins(int* bins, u32 prefix, int need,
                                                u32* sh_pref, int* sh_need, int* sh_tc){
    int tid = threadIdx.x;
    if (tid < 32){
        int c[8]; int lsum = 0;
        #pragma unroll
        for (int j = 0; j < 8; j++){ c[j] = bins[(tid<<3)+j]; lsum += c[j]; }
        int acc = lsum;
        #pragma unroll
        for (int off = 1; off < 32; off <<= 1){
            int t2 = __shfl_down_sync(0xFFFFFFFFu, acc, off);
            if (tid + off < 32) acc += t2;
        }
        int cum = acc - lsum;      // count with higher digit
        #pragma unroll
        for (int j = 7; j >= 0; j--){
            int nx = cum + c[j];
            if (cum < need && need <= nx){
                *sh_pref = (prefix << 8) | (u32)((tid<<3) + j);
                *sh_need = need - cum;
                *sh_tc   = c[j];
            }
            cum = nx;
        }
    }
}

template<int NK>
__device__ u32 radix_select32(const u64* key, bool lo_mode, u32 hi_match, bool act_pos, int T,
                              int* bins, u32* sh_pref, int* sh_need, int* sh_tc,
                              int* ret_need, int* ret_tc){
    u32 prefix = 0; int need = T, tc = 0;
    for (int pass = 0; pass < 4; pass++){
        const int shift = 24 - (pass<<3);
        for (int i = threadIdx.x; i < 256; i += blockDim.x) bins[i] = 0;
        __syncthreads();
        #pragma unroll
        for (int q = 0; q < NK; q++){
            u64 k = key[q];
            if (k){
                u32 hi = (u32)(k >> 32);
                u32 f  = lo_mode ? (u32)k : hi;
                bool ok = (!act_pos || (hi & 0x80000000u)) &&
                          (!lo_mode || hi == hi_match) &&
                          (pass == 0 || (f >> (shift+8)) == prefix);
                if (ok) atomicAdd(&bins[(f >> shift) & 255], 1);
            }
        }
        __syncthreads();
        radix_scan_bins(bins, prefix, need, sh_pref, sh_need, sh_tc);
        __syncthreads();
        prefix = *sh_pref; need = *sh_need; tc = *sh_tc;
        __syncthreads();
    }
    *ret_need = need; *ret_tc = tc;
    return prefix;
}

template<int NK>
__device__ u64 topk_thr(const u64* key, bool act_pos, int T,
                        int* bins, u32* shp, int* shn, int* sht){
    int need2, tc;
    u32 thr_hi = radix_select32<NK>(key, false, 0, act_pos, T, bins, shp, shn, sht, &need2, &tc);
    u32 thr_lo = 0;
    if (tc != need2){
        int d1, d2;
        thr_lo = radix_select32<NK>(key, true, thr_hi, act_pos, need2, bins, shp, shn, sht, &d1, &d2);
    }
    return ((u64)thr_hi << 32) | thr_lo;
}

// ================= per (image,class): counting-sort rank + greedy NMS (256 threads) =================
__global__ __launch_bounds__(256) void k_classnms(const float* __restrict__ pred){
    const int p = blockIdx.x;
    const int tid = threadIdx.x;
    const int bimg = p / NC;

    __shared__ float2 s_dims[45];
    __shared__ int bins[256], base[256], cur[256];
    __shared__ int s_cnt, s_tbmin, s_tbmax;
    __shared__ u64 s_ord[CAP];
    __shared__ float4 sbox[KMAX];
    __shared__ float sarea[KMAX], ssc[KMAX];
    __shared__ u32 supw[KMAX*4];
    __shared__ u32 s_keep[4];

    if (tid < 45) s_dims[tid] = g_dims2[tid];   // L2 hit, no FP64 here

    int cnt = g_cnt[p<<CSH];

    // exact fallback (block-uniform; never taken on this data, guards any data)
    if (cnt < KMAX || cnt > CAP){
        const int c = p % NC;
        const float* bptr = pred + (size_t)bimg*NANCH*NF + 4 + c;
        if (tid == 0) s_cnt = 0;
        __syncthreads();
        int loc = 0;
        for (int n = tid; n < NANCH; n += 256)
            if (sigmoidf_(bptr[(size_t)n*NF]) > SCORE_TH) loc++;
        atomicAdd(&s_cnt, loc);
        __syncthreads();
        int total = s_cnt;
        int T0 = min(total, KMAX);
        if (T0 == 0) cnt = 0;
        else {
            u64 lo = 0ull, hi = ~0ull;
            while (lo < hi){
                u64 mid = lo + ((hi - lo) >> 1) + 1ull;
                __syncthreads();
                if (tid == 0) s_cnt = 0;
                __syncthreads();
                int cc = 0;
                for (int n = tid; n < NANCH; n += 256){
                    float v = bptr[(size_t)n*NF];
                    if (sigmoidf_(v) > SCORE_TH){
                        u64 kk = ((u64)flip_f(__float_as_uint(v)) << 32) | (u32)(0x7FFFFFFF - n);
                        if (kk >= mid) cc++;
                    }
                }
                atomicAdd(&s_cnt, cc);
                __syncthreads();
                if (s_cnt >= T0) lo = mid; else hi = mid - 1;
            }
            __syncthreads();
            if (tid == 0) s_cnt = 0;
            __syncthreads();
            for (int n = tid; n < NANCH; n += 256){
                float v = bptr[(size_t)n*NF];
                if (sigmoidf_(v) > SCORE_TH){
                    u64 kk = ((u64)flip_f(__float_as_uint(v)) << 32) | (u32)(0x7FFFFFFF - n);
                    if (kk >= lo){
                        int sl = atomicAdd(&s_cnt, 1);
                        if (sl < CAP) g_cand[p*CAP + sl] = kk;
                    }
                }
            }
            cnt = T0;
        }
        __syncthreads();
    }

    const int T = min(cnt, KMAX);

    // load keys to registers
    u64 key[2];
    #pragma unroll
    for (int q = 0; q < 2; q++){
        int s = tid + (q<<8);
        key[q] = (s < cnt) ? g_cand[p*CAP + s] : 0ull;
    }

    if (tid == 0){ s_tbmin = 256; s_tbmax = -1; }
    bins[tid] = 0;
    if (tid < KMAX){ ssc[tid] = -1.0f; sbox[tid] = make_float4(0,0,0,0); sarea[tid] = 0.0f; }
    if (tid < KMAX*4 - 256) supw[tid+256] = 0u;
    supw[tid] = 0u;
    __syncthreads();

    // top-byte uniformity check (chooses exact binning byte)
    #pragma unroll
    for (int q = 0; q < 2; q++){
        if (key[q]){
            int tb = (int)((u32)(key[q] >> 56));
            atomicMin(&s_tbmin, tb);
            atomicMax(&s_tbmax, tb);
        }
    }
    __syncthreads();
    const bool by23 = (s_tbmin == s_tbmax);   // all top bytes equal -> bin by bits[55:48] of key

    // histogram
    #pragma unroll
    for (int q = 0; q < 2; q++){
        if (key[q]){
            int b = by23 ? (int)((key[q] >> 48) & 255) : (int)((u32)(key[q] >> 56));
            atomicAdd(&bins[b], 1);
        }
    }
    __syncthreads();

    // descending exclusive prefix: base[b] = #keys in bins > b; cur = running cursor
    if (tid < 32){
        int c[8]; int lsum = 0;
        #pragma unroll
        for (int j = 0; j < 8; j++){ c[j] = bins[(tid<<3)+j]; lsum += c[j]; }
        int acc = lsum;
        #pragma unroll
        for (int off = 1; off < 32; off <<= 1){
            int t2 = __shfl_down_sync(0xFFFFFFFFu, acc, off);
            if (tid + off < 32) acc += t2;
        }
        int cum = acc - lsum;
        #pragma unroll
        for (int j = 7; j >= 0; j--){
            base[(tid<<3)+j] = cum;
            cur[(tid<<3)+j]  = cum;
            cum += c[j];
        }
    }
    __syncthreads();

    // scatter into bin-grouped order
    #pragma unroll
    for (int q = 0; q < 2; q++){
        if (key[q]){
            int b = by23 ? (int)((key[q] >> 48) & 255) : (int)((u32)(key[q] >> 56));
            int slot = atomicAdd(&cur[b], 1);
            s_ord[slot] = key[q];
        }
    }
    __syncthreads();

    // exact rank = base[b] + #same-bin keys greater; only bins reaching rank<T matter
    #pragma unroll
    for (int q = 0; q < 2; q++){
        if (key[q]){
            u64 k = key[q];
            int b = by23 ? (int)((k >> 48) & 255) : (int)((u32)(k >> 56));
            int lo = base[b];
            if (lo < T){                       // skip keys that cannot be winners
                int hiB = lo + bins[b];
                int rank = lo;
                for (int t = lo; t < hiB; t++) rank += (s_ord[t] > k);
                if (rank < T){
                    float logit = unflip_f((u32)(k >> 32));
                    float sc = sigmoidf_(logit);
                    int n = 0x7FFFFFFF - (int)(u32)(k & 0xFFFFFFFFull);
                    int lvl = (n>=57600) + (n>=72000) + (n>=75600) + (n>=76500);
                    int off = (lvl==0)?0 : (lvl==1)?57600 : (lvl==2)?72000 : (lvl==3)?75600 : 76500;
                    int local = n - off;
                    int k9   = local % 9;
                    int cell = local / 9;
                    int sh = 4 - lvl;
                    int iy = (cell/5) >> sh;
                    int jx = cell - iy*(5<<sh);
                    float stridef = (float)(8<<lvl);
                    float2 d = s_dims[lvl*9 + k9];
                    float4 bp = __ldg((const float4*)pred + (size_t)(bimg*NANCH + n)*21);
                    float cx = ((float)jx + 0.5f)*stridef;
                    float cy = ((float)iy + 0.5f)*stridef;
                    float x  = (bp.x*0.1f)*d.x + cx;
                    float y  = (bp.y*0.1f)*d.y + cy;
                    float ww = expf(bp.z*0.2f)*d.x;
                    float hh = expf(bp.w*0.2f)*d.y;
                    float4 bx = make_float4(x - ww*0.5f, y - hh*0.5f, x + ww*0.5f, y + hh*0.5f);
                    ssc[rank] = sc;
                    sbox[rank] = bx;
                    sarea[rank] = (bx.z - bx.x)*(bx.w - bx.y);
                }
            }
        }
    }
    __syncthreads();

    // pair-parallel suppression masks: tournament (circle) map, 4950 fixed pairs.
    for (int q = tid; q < (KMAX*(KMAX-1))/2; q += 256){
        int r = q / 50, m = q - r*50;     // round, match
        int i, j;
        if (m == 0){ i = r; j = KMAX-1; }
        else {
            int a = r + m;            if (a >= KMAX-1) a -= (KMAX-1);
            int bb = r + (KMAX-1) - m; if (bb >= KMAX-1) bb -= (KMAX-1);
            i = min(a,bb); j = max(a,bb);
        }
        float4 A = sbox[i], B = sbox[j];
        float ltx = fmaxf(A.x,B.x), lty = fmaxf(A.y,B.y);
        float rbx = fminf(A.z,B.z), rby = fminf(A.w,B.w);
        float w = fmaxf(rbx-ltx, 0.0f), h = fmaxf(rby-lty, 0.0f);
        float inter = w*h;
        float iou = inter / (sarea[i] + sarea[j] - inter + 1e-8f);
        if (iou > IOU_THR)
            atomicOr(&supw[i*4 + (j>>5)], 1u << (j & 31));
    }
    __syncthreads();

    // sequential greedy on 4x u32 masks (exact reference semantics)
    if (tid == 0){
        u32 keep[4];
        #pragma unroll
        for (int w = 0; w < 4; w++){
            int rem = T - w*32;
            keep[w] = (rem >= 32) ? 0xFFFFFFFFu : (rem <= 0 ? 0u : ((1u<<rem)-1u));
        }
        for (int i = 0; i < T; i++){
            if (keep[i>>5] & (1u << (i&31))){
                keep[0] &= ~supw[i*4+0]; keep[1] &= ~supw[i*4+1];
                keep[2] &= ~supw[i*4+2]; keep[3] &= ~supw[i*4+3];
            }
        }
        s_keep[0]=keep[0]; s_keep[1]=keep[1]; s_keep[2]=keep[2]; s_keep[3]=keep[3];
        g_cnt[p<<CSH] = 0;    // re-arm for next launch/replay
    }
    __syncthreads();
    if (tid < KMAX){
        bool kept = (tid < T) && (s_keep[tid>>5] & (1u << (tid&31)));
        g_cls_scores[p*KMAX + tid] = kept ? ssc[tid] : -1.0f;
        ((float4*)g_cls_boxes)[p*KMAX + tid] = sbox[tid];
    }
}

// ================= per image merge: top-100 of 8000, write outputs (512 threads) =================
__global__ __launch_bounds__(512) void k_merge(float* __restrict__ out){
    const int b = blockIdx.x;
    const int tid = threadIdx.x;
    const int M = NC*KMAX;   // 8000

    u64 key[16];
    int npos_loc = 0;
    #pragma unroll
    for (int q = 0; q < 16; q++){
        int s = tid + (q<<9);
        u64 kk = 0ull;
        if (s < M){
            float sc = g_cls_scores[b*M + s];
            kk = ((u64)flip_f(__float_as_uint(sc)) << 32) | (u32)(0x7FFFFFFF - s);
            if (sc > 0.0f) npos_loc++;
        }
        key[q] = kk;
    }

    __shared__ int bins[256];
    __shared__ u32 sh_pref; __shared__ int sh_need, sh_tc;
    __shared__ int s_n, s_valid, s_npos;
    __shared__ u64 s_key[112];
    __shared__ u64 s_sorted[KMAX];

    if (tid == 0){ s_n = 0; s_valid = 0; s_npos = 0; }
    if (tid < KMAX) s_sorted[tid] = 0ull;
    __syncthreads();
    for (int o = 16; o; o >>= 1) npos_loc += __shfl_down_sync(0xFFFFFFFFu, npos_loc, o);
    if ((tid & 31) == 0 && npos_loc) atomicAdd(&s_npos, npos_loc);
    __syncthreads();
    const bool pos_only = (s_npos >= KMAX);  // true on real data; rare path stays exact

    u64 thr = topk_thr<16>(key, pos_only, KMAX, bins, &sh_pref, &sh_need, &sh_tc);

    #pragma unroll
    for (int q = 0; q < 16; q++){
        u64 k = key[q];
        bool act = k && (!pos_only || ((u32)(k>>32) & 0x80000000u));
        if (act && k >= thr){
            int pos = atomicAdd(&s_n, 1);
            if (pos < 112) s_key[pos] = k;
        }
    }
    __syncthreads();
    const int mG = min(s_n, 112);

    if (tid < mG){
        u64 k = s_key[tid];
        int rank = 0;
        for (int jj = 0; jj < mG; jj++) rank += (s_key[jj] > k);
        if (rank < KMAX) s_sorted[rank] = k;
    }
    __syncthreads();

    if (tid < KMAX){
        u64 k = s_sorted[tid];
        float sc = unflip_f((u32)(k >> 32));
        int s = 0x7FFFFFFF - (int)(u32)(k & 0xFFFFFFFFull);
        bool good = (k != 0ull) && (sc > 0.0f);
        float4 bx = make_float4(0,0,0,0); float clsf = 0.0f;
        if (good){
            bx = ((const float4*)g_cls_boxes)[b*M + s];
            clsf = (float)(s / KMAX);
            atomicAdd(&s_valid, 1);
        }
        ((float4*)out)[b*KMAX + tid] = bx;                       // boxes  [0, 3200)
        out[BATCH*KMAX*4 + b*KMAX + tid] = good ? sc : 0.0f;     // scores [3200, 4000)
        out[BATCH*KMAX*5 + b*KMAX + tid] = clsf;                 // classes[4000, 4800)
    }
    __syncthreads();
    if (tid == 0) out[BATCH*KMAX*6 + b] = (float)s_valid;        // valid  [4800, 4808)
}

extern "C" void kernel_launch(void* const* d_in, const int* in_sizes, int n_in,
                              void* d_out, int out_size){
    const float* pred = nullptr;
    const int PRED_SZ = BATCH*NANCH*NF;
    int best = -1;
    for (int i = 0; i < n_in; i++){
        if (in_sizes[i] == PRED_SZ){ pred = (const float*)d_in[i]; break; }
        if (best < 0 || in_sizes[i] > in_sizes[best]) best = i;
    }
    if (!pred) pred = (const float*)d_in[best < 0 ? 0 : best];

    float* out = (float*)d_out;
    (void)out_size;

    k_scan<<<2048, 256>>>((const float4*)pred);
    k_classnms<<<NPAIR, 256>>>(pred);
    k_merge<<<BATCH, 512>>>(out);
}